// round 10
// baseline (speedup 1.0000x reference)
#include <cuda_runtime.h>

// FeatureInteraction: B=16384, F=27, D=128
// out[b] = concat(embeddings[b].flatten() (3456), triu(E E^T, k=1) (351)) -> 3807 floats
//
// R10: persistent-ish pipeline. Block = 4 warps on ONE batch element
//      (d-quartile per warp, closed under XOR swizzle -> no cross-warp staging
//      deps). NITER=16 batch elements per block, double-buffered cp.async
//      prefetch overlaps DRAM latency with compute. Reduction scratch lives in
//      the just-consumed (dead) slot.

static constexpr int F      = 27;
static constexpr int F_PAD  = 28;
static constexpr int D      = 128;
static constexpr int FLAT   = F * D;              // 3456
static constexpr int NPAIR  = (F * (F - 1)) / 2;  // 351
static constexpr int ROWLEN = FLAT + NPAIR;       // 3807
static constexpr int SLOT   = F_PAD * D;          // 3584 words
static constexpr int NITER  = 16;                 // batch elements per block
static constexpr int THREADS = 128;
static constexpr int SCR_TRIU = 1792;             // triu scratch inside dead slot

__device__ __forceinline__ unsigned long long pack2(float x, float y) {
    unsigned long long r;
    asm("mov.b64 %0, {%1, %2};" : "=l"(r) : "f"(x), "f"(y));
    return r;
}
__device__ __forceinline__ void unpack2(unsigned long long v, float& x, float& y) {
    asm("mov.b64 {%0, %1}, %2;" : "=f"(x), "=f"(y) : "l"(v));
}
__device__ __forceinline__ void ffma2(unsigned long long& acc,
                                      unsigned long long a, unsigned long long b) {
    asm("fma.rn.f32x2 %0, %1, %2, %0;" : "+l"(acc) : "l"(a), "l"(b));
}
__device__ __forceinline__ void cp_async16(unsigned smem_addr, const void* gptr, int src_sz) {
    asm volatile("cp.async.cg.shared.global [%0], [%1], 16, %2;"
                 :: "r"(smem_addr), "l"(gptr), "r"(src_sz));
}

// Issue this warp's quartile of batch b into slot buf: 7 cp.async.cg per lane.
// Row 27 (pad) zero-filled via src_size=0 (valid src addr, never read).
__device__ __forceinline__ void stage_issue(float* buf, const float* inb, int w, int lane) {
    const float4* g = reinterpret_cast<const float4*>(inb);
    #pragma unroll
    for (int k = 0; k < 7; ++k) {
        const int idx = k * 32 + lane;            // 0..223
        const int f   = idx >> 3;                 // 0..27 (27 = pad)
        const int c   = 8 * w + (idx & 7);        // chunk within row
        const unsigned sa = (unsigned)__cvta_generic_to_shared(
            buf + f * D + ((c ^ (f >> 2)) << 2));
        cp_async16(sa, (f < F) ? (const void*)(g + f * 32 + c) : (const void*)g,
                   (f < F) ? 16 : 0);
    }
}

__global__ void __launch_bounds__(THREADS, 7)
fi_kernel(const float* __restrict__ in, float* __restrict__ out, int batch)
{
    __shared__ float sm[2 * SLOT];                // 28672 B

    const int tid  = threadIdx.x;
    const int w    = tid >> 5;                    // warp 0..3 = d-quartile
    const int lane = tid & 31;
    const long nbase = (long)blockIdx.x * NITER;

    // lane -> 4x4 tile coords of the 7x7 tile grid (same mapping every warp)
    int ti = 0, tj = 0;
    if (lane < 28) {
        int l = lane, cnt = 7;
        while (l >= cnt) { l -= cnt; ++ti; --cnt; }
        tj = ti + l;
    }

    // ---- prologue: stage batch nbase into slot 0 ----
    if (nbase < batch)
        stage_issue(sm, in + (size_t)nbase * FLAT, w, lane);
    asm volatile("cp.async.commit_group;" ::: "memory");

    for (int i = 0; i < NITER; ++i) {
        const long b = nbase + i;
        if (b >= batch) break;
        float* cur = sm + ((i & 1) ? SLOT : 0);
        float* nxt = sm + ((i & 1) ? 0 : SLOT);

        // prefetch next batch element into the other slot
        if (i + 1 < NITER && b + 1 < batch)
            stage_issue(nxt, in + (size_t)(b + 1) * FLAT, w, lane);
        asm volatile("cp.async.commit_group;" ::: "memory");
        asm volatile("cp.async.wait_group 1;" ::: "memory");  // batch b landed
        __syncwarp();   // make all lanes' cp.async results visible warp-wide

        float* outb = out + (size_t)b * ROWLEN;

        // ---- flat output: own 32-word window of each row (de-swizzled LDS,
        // coalesced STG) ----
        #pragma unroll 9
        for (int f = 0; f < F; ++f) {
            const int d = 32 * w + lane;
            outb[f * D + d] =
                cur[f * D + ((((d >> 2) ^ (f >> 2)) << 2) | (d & 3))];
        }

        // ---- partial gram over this warp's chunks [8w, 8w+8) ----
        float val[4][4];
        if (lane < 28) {
            unsigned long long acc[4][4];
            #pragma unroll
            for (int r = 0; r < 4; ++r)
                #pragma unroll
                for (int c = 0; c < 4; ++c) acc[r][c] = 0ull;

            const float* pi = cur + (4 * ti) * D;
            const float* pj = cur + (4 * tj) * D;

            #pragma unroll 2
            for (int c = 8 * w; c < 8 * w + 8; ++c) {
                const int ci = (c ^ ti) << 2;
                const int cj = (c ^ tj) << 2;
                float4 ai4[4], aj4[4];
                #pragma unroll
                for (int r = 0; r < 4; ++r)
                    ai4[r] = *reinterpret_cast<const float4*>(pi + r * D + ci);
                #pragma unroll
                for (int cc = 0; cc < 4; ++cc)
                    aj4[cc] = *reinterpret_cast<const float4*>(pj + cc * D + cj);

                unsigned long long ailo[4], aihi[4], ajlo[4], ajhi[4];
                #pragma unroll
                for (int r = 0; r < 4; ++r) {
                    ailo[r] = pack2(ai4[r].x, ai4[r].y);
                    aihi[r] = pack2(ai4[r].z, ai4[r].w);
                }
                #pragma unroll
                for (int cc = 0; cc < 4; ++cc) {
                    ajlo[cc] = pack2(aj4[cc].x, aj4[cc].y);
                    ajhi[cc] = pack2(aj4[cc].z, aj4[cc].w);
                }
                #pragma unroll
                for (int r = 0; r < 4; ++r)
                    #pragma unroll
                    for (int cc = 0; cc < 4; ++cc) {
                        ffma2(acc[r][cc], ailo[r], ajlo[cc]);
                        ffma2(acc[r][cc], aihi[r], ajhi[cc]);
                    }
            }
            #pragma unroll
            for (int r = 0; r < 4; ++r)
                #pragma unroll
                for (int cc = 0; cc < 4; ++cc) {
                    float lo, hi;
                    unpack2(acc[r][cc], lo, hi);
                    val[r][cc] = lo + hi;
                }
        }
        __syncthreads();   // bar1: all reads of cur done -> slot is scratch

        // ---- all 4 warps deposit 16 partials each (scratch words 0..1791) ----
        if (lane < 28) {
            #pragma unroll
            for (int v = 0; v < 16; ++v)
                cur[w * 448 + v * 28 + lane] = val[v >> 2][v & 3];
        }
        __syncthreads();   // bar2

        // ---- warp w reduces r=w of every tile; scatter triu into scratch ----
        if (lane < 28) {
            #pragma unroll
            for (int v = 4 * w; v < 4 * w + 4; ++v) {
                const float s = cur[0 * 448 + v * 28 + lane]
                              + cur[1 * 448 + v * 28 + lane]
                              + cur[2 * 448 + v * 28 + lane]
                              + cur[3 * 448 + v * 28 + lane];
                const int r = v >> 2, cc = v & 3;
                const int ii = 4 * ti + r, jj = 4 * tj + cc;
                if (ii < jj && jj < F)
                    cur[SCR_TRIU + ii * F - (ii * (ii + 1)) / 2 + (jj - ii - 1)] = s;
            }
        }
        __syncthreads();   // bar3

        // ---- coalesced triu store (all 128 threads) ----
        #pragma unroll
        for (int j = 0; j < 3; ++j) {
            const int x = tid + 128 * j;
            if (x < NPAIR) outb[FLAT + x] = cur[SCR_TRIU + x];
        }
        __syncthreads();   // bar4: protect scratch from next prefetch into cur
    }
}

extern "C" void kernel_launch(void* const* d_in, const int* in_sizes, int n_in,
                              void* d_out, int out_size)
{
    const float* in = (const float*)d_in[0];
    float* out = (float*)d_out;
    const int batch = in_sizes[0] / FLAT;                  // 16384
    const int grid = (batch + NITER - 1) / NITER;          // 1024
    fi_kernel<<<grid, THREADS>>>(in, out, batch);
}

// round 11
// speedup vs baseline: 1.0860x; 1.0860x over previous
#include <cuda_runtime.h>

// FeatureInteraction: B=16384, F=27, D=128
// out[b] = concat(embeddings[b].flatten() (3456), triu(E E^T, k=1) (351)) -> 3807 floats
//
// R11: block = ONE warp-pair (64 thr) on one batch element at a time, d-half
//      per warp; NITER=8 batches per block with 2-slot cp.async double buffer.
//      Prefetch of batch i+1 issued before computing batch i -> DRAM latency
//      overlapped by pipelining, not occupancy. Pair-scope __syncthreads only.

static constexpr int F      = 27;
static constexpr int F_PAD  = 28;
static constexpr int D      = 128;
static constexpr int HALF   = 64;
static constexpr int FLAT   = F * D;              // 3456
static constexpr int NPAIR  = (F * (F - 1)) / 2;  // 351
static constexpr int ROWLEN = FLAT + NPAIR;       // 3807
static constexpr int SLOT   = F_PAD * D;          // 3584 words
static constexpr int NITER  = 8;                  // batch elements per block
static constexpr int THREADS = 64;

__device__ __forceinline__ unsigned long long pack2(float x, float y) {
    unsigned long long r;
    asm("mov.b64 %0, {%1, %2};" : "=l"(r) : "f"(x), "f"(y));
    return r;
}
__device__ __forceinline__ void unpack2(unsigned long long v, float& x, float& y) {
    asm("mov.b64 {%0, %1}, %2;" : "=f"(x), "=f"(y) : "l"(v));
}
__device__ __forceinline__ void ffma2(unsigned long long& acc,
                                      unsigned long long a, unsigned long long b) {
    asm("fma.rn.f32x2 %0, %1, %2, %0;" : "+l"(acc) : "l"(a), "l"(b));
}
__device__ __forceinline__ void cp_async16(unsigned smem_addr, const void* gptr, int src_sz) {
    asm volatile("cp.async.cg.shared.global [%0], [%1], 16, %2;"
                 :: "r"(smem_addr), "l"(gptr), "r"(src_sz));
}

// Row f = words [f*128, f*128+128); 16B chunk c stored at slot c ^ (f>>2).
__device__ __forceinline__ int sm_word(int f, int d) {
    return f * D + ((((d >> 2) ^ (f >> 2)) << 2) | (d & 3));
}

// Issue this warp's d-half of one batch tile: 14 cp.async.cg (16B) per lane.
// Pad row 27 zero-filled via src_size=0.
__device__ __forceinline__ void stage_issue(float* buf, const float* inb,
                                            int dh, int lane) {
    const int g  = lane >> 4;
    const int cq = (lane & 15) + dh * 16;         // chunk 0..31 within row
    const float4* g4 = reinterpret_cast<const float4*>(inb);
    #pragma unroll
    for (int k = 0; k < 14; ++k) {
        const int f = 2 * k + g;                  // 0..27 (27 = pad)
        const unsigned sa = (unsigned)__cvta_generic_to_shared(
            buf + f * D + ((cq ^ (f >> 2)) << 2));
        cp_async16(sa, (f < F) ? (const void*)(g4 + f * 32 + cq) : (const void*)g4,
                   (f < F) ? 16 : 0);
    }
}

__global__ void __launch_bounds__(THREADS, 7)
fi_kernel(const float* __restrict__ in, float* __restrict__ out, int batch)
{
    __shared__ float sm[2 * SLOT];                // 28672 B

    const int tid  = threadIdx.x;
    const int dh   = tid >> 5;                    // warp = d-half
    const int lane = tid & 31;
    const long b0  = (long)blockIdx.x * NITER;

    // lane -> 4x4 tile coords of the 7x7 tile grid over the triangle
    int ti = 0, tj = 0;
    if (lane < 28) {
        int l = lane, cnt = 7;
        while (l >= cnt) { l -= cnt; ++ti; --cnt; }
        tj = ti + l;
    }

    // ---- prologue: stage batch b0 into slot 0 ----
    if (b0 < batch)
        stage_issue(sm, in + (size_t)b0 * FLAT, dh, lane);
    asm volatile("cp.async.commit_group;" ::: "memory");

    for (int i = 0; i < NITER; ++i) {
        const long b = b0 + i;
        if (b >= batch) break;
        float* cur = sm + ((i & 1) ? SLOT : 0);
        float* nxt = sm + ((i & 1) ? 0 : SLOT);

        // prefetch batch b+1 into the other slot (overlaps with compute below)
        if (i + 1 < NITER && b + 1 < batch)
            stage_issue(nxt, in + (size_t)(b + 1) * FLAT, dh, lane);
        asm volatile("cp.async.commit_group;" ::: "memory");
        asm volatile("cp.async.wait_group 1;" ::: "memory");  // batch b landed
        __syncwarp();

        float* outb = out + (size_t)b * ROWLEN;

        // ---- flat output: own d-half, de-swizzled LDS -> coalesced STG ----
        #pragma unroll 6
        for (int it = 0; it < F * 2; ++it) {      // 54 iters
            const int f = it >> 1;
            const int d = dh * HALF + ((it & 1) << 5) + lane;
            outb[f * D + d] = cur[sm_word(f, d)];
        }

        // ---- partial gram over this warp's chunks [16dh, 16dh+16) ----
        float val[4][4];
        if (lane < 28) {
            unsigned long long acc[4][4];
            #pragma unroll
            for (int r = 0; r < 4; ++r)
                #pragma unroll
                for (int c = 0; c < 4; ++c) acc[r][c] = 0ull;

            const float* pi = cur + (4 * ti) * D;
            const float* pj = cur + (4 * tj) * D;

            const int c0 = dh * 16;
            #pragma unroll 2
            for (int c = c0; c < c0 + 16; ++c) {
                const int ci = (c ^ ti) << 2;
                const int cj = (c ^ tj) << 2;
                float4 ai4[4], aj4[4];
                #pragma unroll
                for (int r = 0; r < 4; ++r)
                    ai4[r] = *reinterpret_cast<const float4*>(pi + r * D + ci);
                #pragma unroll
                for (int cc = 0; cc < 4; ++cc)
                    aj4[cc] = *reinterpret_cast<const float4*>(pj + cc * D + cj);

                unsigned long long ailo[4], aihi[4], ajlo[4], ajhi[4];
                #pragma unroll
                for (int r = 0; r < 4; ++r) {
                    ailo[r] = pack2(ai4[r].x, ai4[r].y);
                    aihi[r] = pack2(ai4[r].z, ai4[r].w);
                }
                #pragma unroll
                for (int cc = 0; cc < 4; ++cc) {
                    ajlo[cc] = pack2(aj4[cc].x, aj4[cc].y);
                    ajhi[cc] = pack2(aj4[cc].z, aj4[cc].w);
                }
                #pragma unroll
                for (int r = 0; r < 4; ++r)
                    #pragma unroll
                    for (int cc = 0; cc < 4; ++cc) {
                        ffma2(acc[r][cc], ailo[r], ajlo[cc]);
                        ffma2(acc[r][cc], aihi[r], ajhi[cc]);
                    }
            }
            #pragma unroll
            for (int r = 0; r < 4; ++r)
                #pragma unroll
                for (int cc = 0; cc < 4; ++cc) {
                    float lo, hi;
                    unpack2(acc[r][cc], lo, hi);
                    val[r][cc] = lo + hi;
                }
        }
        __syncwarp();   // this warp's reads of cur done; its columns = scratch

        // ---- warp dh==1 deposits 448 partials into its dead columns ----
        if (lane < 28 && dh == 1) {
            #pragma unroll
            for (int v = 0; v < 16; ++v) {
                const int w = v * 28 + lane;
                cur[(w >> 6) * D + HALF + (w & 63)] = val[v >> 2][v & 3];
            }
        }
        __syncthreads();   // bar1: deposits visible to dh0

        // ---- dh==0 reduces, scatters triu into its dead columns, stores ----
        if (dh == 0) {
            if (lane < 28) {
                #pragma unroll
                for (int v = 0; v < 16; ++v) {
                    const int w = v * 28 + lane;
                    const float s = val[v >> 2][v & 3]
                                  + cur[(w >> 6) * D + HALF + (w & 63)];
                    const int r = v >> 2, cc = v & 3;
                    const int ii = 4 * ti + r, jj = 4 * tj + cc;
                    if (ii < jj && jj < F)
                        cur[(ii * F - (ii * (ii + 1)) / 2 + (jj - ii - 1)) / HALF * D
                            + ((ii * F - (ii * (ii + 1)) / 2 + (jj - ii - 1)) & 63)]
                            = s;
                }
            }
            __syncwarp();
            float* outp = outb + FLAT;
            #pragma unroll
            for (int it = 0; it < (NPAIR + 31) / 32; ++it) {
                const int x = it * 32 + lane;
                if (x < NPAIR) outp[x] = cur[(x >> 6) * D + (x & 63)];
            }
        }
        __syncthreads();   // bar2: scratch reads done before re-staging cur
    }
}

extern "C" void kernel_launch(void* const* d_in, const int* in_sizes, int n_in,
                              void* d_out, int out_size)
{
    const float* in = (const float*)d_in[0];
    float* out = (float*)d_out;
    const int batch = in_sizes[0] / FLAT;                  // 16384
    const int grid = (batch + NITER - 1) / NITER;          // 2048
    fi_kernel<<<grid, THREADS>>>(in, out, batch);
}